// round 1
// baseline (speedup 1.0000x reference)
#include <cuda_runtime.h>
#include <math.h>

#define N_S 100000
#define N_I 100000
#define E_EDGES 3200000
#define D 16
#define H 32

// ---------------- scratch (device globals; no allocation allowed) ----------------
__device__ __align__(16) float g_Ms[N_S * H];      // msg features, served
__device__ __align__(16) float g_Mi[N_I * H];      // msg features, interfered
__device__ __align__(16) float g_as[N_S * H];      // aggr into served
__device__ __align__(16) float g_ai[N_I * H];      // aggr into interfered
__device__ __align__(16) float g_xs[2][N_S * D];   // ping-pong node feats
__device__ __align__(16) float g_xi[2][N_I * D];
__device__ __align__(16) float g_bfm[N_S * D];
__device__ float g_ss[16];
__device__ __align__(16) float g_scale[16];

__device__ __forceinline__ float lrelu(float x) { return fmaxf(x, 0.01f * x); }

// ---------------- msg MLP: M = lrelu(lrelu(x@Wm1+b)@Wm2+b)  (warp per node) ----
// Also zeroes the aggregation buffers (completes before scatter launch) and g_ss.
__global__ void msg_kernel(const float* __restrict__ xs_ext,
                           const float* __restrict__ xi_ext,
                           const float* __restrict__ Wm1, const float* __restrict__ bm1,
                           const float* __restrict__ Wm2, const float* __restrict__ bm2,
                           int inbuf)
{
    __shared__ float sW1[16 * 32];
    __shared__ float sW2[32 * 32];
    __shared__ float sb1[32];
    __shared__ float sb2[32];

    int tid = threadIdx.x;
    for (int i = tid; i < 16 * 32; i += blockDim.x) sW1[i] = Wm1[i];
    for (int i = tid; i < 32 * 32; i += blockDim.x) sW2[i] = Wm2[i];
    if (tid < 32) { sb1[tid] = bm1[tid]; sb2[tid] = bm2[tid]; }

    // zero aggr buffers (float4 grid-stride) + g_ss
    {
        int gtid = blockIdx.x * blockDim.x + tid;
        int nthreads = gridDim.x * blockDim.x;
        float4 z = make_float4(0.f, 0.f, 0.f, 0.f);
        float4* zs = (float4*)g_as;
        float4* zi = (float4*)g_ai;
        const int Q = (N_S * H) / 4;
        for (int i = gtid; i < Q; i += nthreads) { zs[i] = z; zi[i] = z; }
        if (blockIdx.x == 0 && tid < 16) g_ss[tid] = 0.f;
    }
    __syncthreads();

    int lane = tid & 31;
    int gwarp = (blockIdx.x * blockDim.x + tid) >> 5;
    int nwarps = (gridDim.x * blockDim.x) >> 5;

    const float* xs = (inbuf < 0) ? xs_ext : g_xs[inbuf];
    const float* xi = (inbuf < 0) ? xi_ext : g_xi[inbuf];

    for (int node = gwarp; node < N_S + N_I; node += nwarps) {
        bool served = node < N_S;
        const float* x = served ? (xs + node * D) : (xi + (node - N_S) * D);
        float* Mout = served ? (g_Ms + node * H) : (g_Mi + (node - N_S) * H);

        float xv = (lane < D) ? x[lane] : 0.f;

        float h = sb1[lane];
        #pragma unroll
        for (int k = 0; k < 16; k++)
            h += __shfl_sync(0xffffffffu, xv, k) * sW1[k * 32 + lane];
        h = lrelu(h);

        float m = sb2[lane];
        #pragma unroll
        for (int k = 0; k < 32; k++)
            m += __shfl_sync(0xffffffffu, h, k) * sW2[k * 32 + lane];
        m = lrelu(m);

        Mout[lane] = m;
    }
}

// ---------------- scatter: aggr[dst] += M[src] over both edge lists -------------
// 4 edges per warp; 8 lanes per edge each move one float4 via red.global.add.v4.f32
__global__ void scatter_kernel(const int* __restrict__ ei_si,
                               const int* __restrict__ ei_is)
{
    int tid = blockIdx.x * blockDim.x + threadIdx.x;
    int lane = threadIdx.x & 31;
    int v = lane & 7;          // float4 index within the 32-float row
    int sub = lane >> 3;       // which of 4 edges in this warp
    int warpId = tid >> 5;
    int nwarps = (gridDim.x * blockDim.x) >> 5;

    const int totalChunks = (2 * E_EDGES) / 4;

    for (int chunk = warpId; chunk < totalChunks; chunk += nwarps) {
        int e = chunk * 4 + sub;
        const int* ei;
        const float* M;
        float* A;
        int eloc;
        if (e < E_EDGES) { ei = ei_si; eloc = e;            M = g_Ms; A = g_ai; }
        else             { ei = ei_is; eloc = e - E_EDGES;  M = g_Mi; A = g_as; }

        int src = ei[eloc];
        int dst = ei[E_EDGES + eloc];

        const float4 val = *(const float4*)(M + src * H + v * 4);
        float* addr = A + dst * H + v * 4;
        asm volatile("red.global.add.v4.f32 [%0], {%1,%2,%3,%4};"
                     :: "l"(addr), "f"(val.x), "f"(val.y), "f"(val.z), "f"(val.w)
                     : "memory");
    }
}

// ---------------- update MLP (warp per node) ------------------------------------
__global__ void update_kernel(const float* __restrict__ xs_ext,
                              const float* __restrict__ xi_ext,
                              const float* __restrict__ Wu1, const float* __restrict__ bu1,
                              const float* __restrict__ Wu2, const float* __restrict__ bu2,
                              int inbuf, int outbuf)
{
    __shared__ float sW1[48 * 32];
    __shared__ float sW2[32 * 16];
    __shared__ float sb1[32];
    __shared__ float sb2[16];

    int tid = threadIdx.x;
    for (int i = tid; i < 48 * 32; i += blockDim.x) sW1[i] = Wu1[i];
    for (int i = tid; i < 32 * 16; i += blockDim.x) sW2[i] = Wu2[i];
    if (tid < 32) sb1[tid] = bu1[tid];
    if (tid < 16) sb2[tid] = bu2[tid];
    __syncthreads();

    int lane = tid & 31;
    int gwarp = (blockIdx.x * blockDim.x + tid) >> 5;
    int nwarps = (gridDim.x * blockDim.x) >> 5;

    const float* xs = (inbuf < 0) ? xs_ext : g_xs[inbuf];
    const float* xi = (inbuf < 0) ? xi_ext : g_xi[inbuf];

    for (int node = gwarp; node < N_S + N_I; node += nwarps) {
        bool served = node < N_S;
        int loc = served ? node : (node - N_S);
        const float* xold = served ? (xs + loc * D) : (xi + loc * D);
        const float* ag   = served ? (g_as + loc * H) : (g_ai + loc * H);
        float* xnew       = served ? (g_xs[outbuf] + loc * D) : (g_xi[outbuf] + loc * D);

        float a  = ag[lane];
        float xv = (lane < D) ? xold[lane] : 0.f;

        float h = sb1[lane];
        #pragma unroll
        for (int k = 0; k < 16; k++)
            h += __shfl_sync(0xffffffffu, xv, k) * sW1[k * 32 + lane];
        #pragma unroll
        for (int k = 0; k < 32; k++)
            h += __shfl_sync(0xffffffffu, a, k) * sW1[(16 + k) * 32 + lane];
        h = lrelu(h);

        int j = lane & 15;
        float o = sb2[j];
        #pragma unroll
        for (int k = 0; k < 32; k++)
            o += __shfl_sync(0xffffffffu, h, k) * sW2[k * 16 + j];
        o = lrelu(o);

        if (lane < D) xnew[lane] = o;
    }
}

// ---------------- final: bfm = tanh(x_s @ Wo + bo), column sum-of-squares -------
__global__ void final_bfm_kernel(const float* __restrict__ Wo,
                                 const float* __restrict__ bo)
{
    __shared__ float sWo[16 * 16];
    __shared__ float sbo[16];
    __shared__ float ssum[16];

    int tid = threadIdx.x;
    if (tid < 256) sWo[tid] = Wo[tid];
    if (tid < 16) { sbo[tid] = bo[tid]; ssum[tid] = 0.f; }
    __syncthreads();

    int lane = tid & 31;
    int j = lane & 15;
    int half = lane >> 4;
    int gwarp = (blockIdx.x * blockDim.x + tid) >> 5;
    int nwarps = (gridDim.x * blockDim.x) >> 5;

    const float* x = g_xs[0];   // layer 2 writes buf 0
    float acc = 0.f;

    const int npairs = N_S / 2;  // N_S even
    for (int pair = gwarp; pair < npairs; pair += nwarps) {
        int node = pair * 2 + half;
        float xv = x[node * D + j];

        float h = sbo[j];
        #pragma unroll
        for (int k = 0; k < 16; k++)
            h += __shfl_sync(0xffffffffu, xv, (lane & 16) | k) * sWo[k * 16 + j];

        float y = tanhf(h);
        g_bfm[node * D + j] = y;
        acc += y * y;
    }

    atomicAdd(&ssum[j], acc);
    __syncthreads();
    if (tid < 16) atomicAdd(&g_ss[tid], ssum[tid]);
}

__global__ void scale_kernel()
{
    int tid = threadIdx.x;   // 16 threads
    int t = tid & 7;
    float n = sqrtf(g_ss[t] + g_ss[t + 8]);
    g_scale[tid] = (n > 1.0f) ? (1.0f / n) : 1.0f;
}

__global__ void out_kernel(float* __restrict__ out)
{
    int gtid = blockIdx.x * blockDim.x + threadIdx.x;
    int nthreads = gridDim.x * blockDim.x;
    const int Q = (N_S * D) / 4;
    const float4* bfm4 = (const float4*)g_bfm;
    const float4* sc4 = (const float4*)g_scale;
    float4* out4 = (float4*)out;
    for (int i = gtid; i < Q; i += nthreads) {
        float4 s = sc4[i & 3];
        float4 b = bfm4[i];
        b.x *= s.x; b.y *= s.y; b.z *= s.z; b.w *= s.w;
        out4[i] = b;
    }
}

// ---------------- launch --------------------------------------------------------
extern "C" void kernel_launch(void* const* d_in, const int* in_sizes, int n_in,
                              void* d_out, int out_size)
{
    const float* xs  = (const float*)d_in[0];
    const float* xi  = (const float*)d_in[1];
    const int* ei_si = (const int*)d_in[2];
    const int* ei_is = (const int*)d_in[3];
    const float* Wm1 = (const float*)d_in[4];
    const float* bm1 = (const float*)d_in[5];
    const float* Wm2 = (const float*)d_in[6];
    const float* bm2 = (const float*)d_in[7];
    const float* Wu1 = (const float*)d_in[8];
    const float* bu1 = (const float*)d_in[9];
    const float* Wu2 = (const float*)d_in[10];
    const float* bu2 = (const float*)d_in[11];
    const float* Wo  = (const float*)d_in[12];
    const float* bo  = (const float*)d_in[13];

    // layer l: inbuf (-1 = external inputs), outbuf
    const int inbufs[3]  = {-1, 0, 1};
    const int outbufs[3] = { 0, 1, 0};

    for (int l = 0; l < 3; l++) {
        msg_kernel<<<1184, 256>>>(xs, xi, Wm1, bm1, Wm2, bm2, inbufs[l]);
        scatter_kernel<<<2368, 256>>>(ei_si, ei_is);
        update_kernel<<<1184, 256>>>(xs, xi, Wu1, bu1, Wu2, bu2, inbufs[l], outbufs[l]);
    }

    final_bfm_kernel<<<592, 256>>>(Wo, bo);
    scale_kernel<<<1, 16>>>();
    out_kernel<<<1184, 256>>>((float*)d_out);
}

// round 3
// speedup vs baseline: 1.8458x; 1.8458x over previous
#include <cuda_runtime.h>
#include <math.h>

#define N_S 100000
#define N_I 100000
#define NTOT 200000
#define E_EDGES 3200000
#define D 16
#define H 32
#define CHUNK 1024
#define NCHUNK 196   // ceil((NTOT+1)/1024)

// ---------------- scratch (device globals) ----------------
// unified node id space: served = [0,N_S), interfered = [N_S, NTOT)
__device__ __align__(16) float g_M[NTOT * H];     // messages
__device__ __align__(16) float g_A[NTOT * H];     // aggregation (gather output)
__device__ __align__(16) float g_x[NTOT * D];     // node features (in-place per layer)
__device__ int   g_cnt[NTOT];
__device__ int   g_off[NTOT + 1];
__device__ int   g_cur[NTOT];
__device__ int   g_bsum[NCHUNK];
__device__ int   g_boff[NCHUNK];
__device__ int   g_csr[2 * E_EDGES];
__device__ __align__(16) float g_bfm[N_S * D];
__device__ float g_ss[16];
__device__ __align__(16) float g_scale[16];

__device__ __forceinline__ float lrelu(float x) { return fmaxf(x, 0.01f * x); }

// ---------------- CSR build ----------------
__global__ void zero_kernel()
{
    int i = blockIdx.x * blockDim.x + threadIdx.x;
    int n = gridDim.x * blockDim.x;
    for (int k = i; k < NTOT; k += n) g_cnt[k] = 0;
    if (i < 16) g_ss[i] = 0.f;
}

__global__ void hist_kernel(const int* __restrict__ ei_si, const int* __restrict__ ei_is)
{
    int i = blockIdx.x * blockDim.x + threadIdx.x;
    int n = gridDim.x * blockDim.x;
    for (int e = i; e < E_EDGES; e += n) {
        atomicAdd(&g_cnt[N_S + ei_si[E_EDGES + e]], 1);  // dst interfered
        atomicAdd(&g_cnt[ei_is[E_EDGES + e]], 1);        // dst served
    }
}

__global__ void scan1_kernel()
{
    __shared__ int sh[CHUNK];
    int t = threadIdx.x;
    int i = blockIdx.x * CHUNK + t;
    sh[t] = (i < NTOT) ? g_cnt[i] : 0;
    __syncthreads();
    for (int o = CHUNK / 2; o > 0; o >>= 1) {
        if (t < o) sh[t] += sh[t + o];
        __syncthreads();
    }
    if (t == 0) g_bsum[blockIdx.x] = sh[0];
}

__global__ void scan2_kernel()
{
    __shared__ int sh[256];
    int t = threadIdx.x;
    int v = (t < NCHUNK) ? g_bsum[t] : 0;
    sh[t] = v;
    __syncthreads();
    for (int o = 1; o < 256; o <<= 1) {
        int u = (t >= o) ? sh[t - o] : 0;
        __syncthreads();
        sh[t] += u;
        __syncthreads();
    }
    if (t < NCHUNK) g_boff[t] = sh[t] - v;   // exclusive
}

__global__ void scan3_kernel()
{
    __shared__ int sh[CHUNK];
    int t = threadIdx.x;
    int i = blockIdx.x * CHUNK + t;
    int v = (i < NTOT) ? g_cnt[i] : 0;
    sh[t] = v;
    __syncthreads();
    for (int o = 1; o < CHUNK; o <<= 1) {
        int u = (t >= o) ? sh[t - o] : 0;
        __syncthreads();
        sh[t] += u;
        __syncthreads();
    }
    if (i <= NTOT) {
        int off = g_boff[blockIdx.x] + sh[t] - v;   // exclusive prefix
        g_off[i] = off;
        if (i < NTOT) g_cur[i] = off;
    }
}

__global__ void fill_kernel(const int* __restrict__ ei_si, const int* __restrict__ ei_is)
{
    int i = blockIdx.x * blockDim.x + threadIdx.x;
    int n = gridDim.x * blockDim.x;
    for (int e = i; e < E_EDGES; e += n) {
        {   // relation si: src served, dst interfered
            int dst = N_S + ei_si[E_EDGES + e];
            int src = ei_si[e];
            g_csr[atomicAdd(&g_cur[dst], 1)] = src;
        }
        {   // relation is: src interfered, dst served
            int dst = ei_is[E_EDGES + e];
            int src = N_S + ei_is[e];
            g_csr[atomicAdd(&g_cur[dst], 1)] = src;
        }
    }
}

// ---------------- msg MLP from external inputs (thread-per-node) ----------------
__global__ void __launch_bounds__(256) msg0_kernel(
    const float* __restrict__ xs_ext, const float* __restrict__ xi_ext,
    const float* __restrict__ Wm1, const float* __restrict__ bm1,
    const float* __restrict__ Wm2, const float* __restrict__ bm2)
{
    __shared__ __align__(16) float sW1t[32 * 16];   // Wm1 transposed [j][k]
    __shared__ __align__(16) float sW2t[32 * 32];
    __shared__ float sb1[32], sb2[32];
    __shared__ float sm[256 * 33];                   // staging, padded

    int t = threadIdx.x;
    for (int i = t; i < 16 * 32; i += 256) { int k = i >> 5, j = i & 31; sW1t[j * 16 + k] = Wm1[i]; }
    for (int i = t; i < 32 * 32; i += 256) { int k = i >> 5, j = i & 31; sW2t[j * 32 + k] = Wm2[i]; }
    if (t < 32) { sb1[t] = bm1[t]; sb2[t] = bm2[t]; }
    __syncthreads();

    int base = blockIdx.x * 256;
    int node = base + t;
    if (node < NTOT) {
        const float* xp = (node < N_S) ? (xs_ext + node * D) : (xi_ext + (node - N_S) * D);
        float x[16];
        #pragma unroll
        for (int i = 0; i < 4; i++) {
            float4 v = ((const float4*)xp)[i];
            x[4*i] = v.x; x[4*i+1] = v.y; x[4*i+2] = v.z; x[4*i+3] = v.w;
        }
        float h[32];
        #pragma unroll
        for (int j = 0; j < 32; j++) {
            float acc = sb1[j];
            #pragma unroll
            for (int k = 0; k < 16; k += 4) {
                float4 w = *(const float4*)&sW1t[j * 16 + k];
                acc += x[k]*w.x + x[k+1]*w.y + x[k+2]*w.z + x[k+3]*w.w;
            }
            h[j] = lrelu(acc);
        }
        #pragma unroll
        for (int j = 0; j < 32; j++) {
            float acc = sb2[j];
            #pragma unroll
            for (int k = 0; k < 32; k += 4) {
                float4 w = *(const float4*)&sW2t[j * 32 + k];
                acc += h[k]*w.x + h[k+1]*w.y + h[k+2]*w.z + h[k+3]*w.w;
            }
            sm[t * 33 + j] = lrelu(acc);
        }
    }
    __syncthreads();
    int nvalid = min(256, NTOT - base);
    for (int i = t; i < nvalid * H; i += 256) {
        int n = i >> 5, j = i & 31;
        g_M[base * H + i] = sm[n * 33 + j];
    }
}

// ---------------- gather aggregation (warp per dst, CSR) ----------------
__global__ void gather_kernel()
{
    int gtid = blockIdx.x * blockDim.x + threadIdx.x;
    int warpId = gtid >> 5;
    int nwarps = (gridDim.x * blockDim.x) >> 5;
    int lane = threadIdx.x & 31;
    int v = lane & 7;        // float4 slot within 32-float row
    int sub = lane >> 3;     // edge sub-slot (4 edges in flight per warp)

    for (int d = warpId; d < NTOT; d += nwarps) {
        int beg = g_off[d];
        int end = g_off[d + 1];
        float4 acc = make_float4(0.f, 0.f, 0.f, 0.f);
        for (int it = beg + sub; it < end; it += 4) {
            int src = g_csr[it];
            float4 m = *(const float4*)(g_M + src * H + v * 4);
            acc.x += m.x; acc.y += m.y; acc.z += m.z; acc.w += m.w;
        }
        // reduce the 4 sub-slots (lanes differing in bits 3,4)
        #pragma unroll
        for (int o = 8; o <= 16; o <<= 1) {
            acc.x += __shfl_xor_sync(0xffffffffu, acc.x, o);
            acc.y += __shfl_xor_sync(0xffffffffu, acc.y, o);
            acc.z += __shfl_xor_sync(0xffffffffu, acc.z, o);
            acc.w += __shfl_xor_sync(0xffffffffu, acc.w, o);
        }
        if (sub == 0) *(float4*)(g_A + d * H + v * 4) = acc;
    }
}

// ---------------- fused update MLP + next-layer msg MLP (thread-per-node) -------
// 128 threads/block keeps total static smem at ~40 KB (< 48 KB hard limit).
__global__ void __launch_bounds__(128) upd_kernel(
    const float* __restrict__ xs_ext, const float* __restrict__ xi_ext,
    const float* __restrict__ Wu1, const float* __restrict__ bu1,
    const float* __restrict__ Wu2, const float* __restrict__ bu2,
    const float* __restrict__ Wm1, const float* __restrict__ bm1,
    const float* __restrict__ Wm2, const float* __restrict__ bm2,
    int layer)
{
    __shared__ __align__(16) float sWu1t[32 * 48];
    __shared__ __align__(16) float sWu2t[16 * 32];
    __shared__ __align__(16) float sW1t[32 * 16];
    __shared__ __align__(16) float sW2t[32 * 32];
    __shared__ float sbu1[32], sbu2[16], sb1[32], sb2[32];
    __shared__ float smM[128 * 33];
    __shared__ float smX[128 * 17];

    int t = threadIdx.x;
    for (int i = t; i < 48 * 32; i += 128) { int k = i >> 5, j = i & 31; sWu1t[j * 48 + k] = Wu1[i]; }
    for (int i = t; i < 32 * 16; i += 128) { int k = i >> 4, j = i & 15; sWu2t[j * 32 + k] = Wu2[i]; }
    for (int i = t; i < 16 * 32; i += 128) { int k = i >> 5, j = i & 31; sW1t[j * 16 + k] = Wm1[i]; }
    for (int i = t; i < 32 * 32; i += 128) { int k = i >> 5, j = i & 31; sW2t[j * 32 + k] = Wm2[i]; }
    if (t < 32) { sbu1[t] = bu1[t]; sb1[t] = bm1[t]; sb2[t] = bm2[t]; }
    if (t < 16) { sbu2[t] = bu2[t]; }
    __syncthreads();

    int base = blockIdx.x * 128;
    int node = base + t;
    if (node < NTOT) {
        float in[48];
        const float* xp = (layer == 0)
            ? ((node < N_S) ? (xs_ext + node * D) : (xi_ext + (node - N_S) * D))
            : (g_x + node * D);
        #pragma unroll
        for (int i = 0; i < 4; i++) {
            float4 vv = ((const float4*)xp)[i];
            in[4*i] = vv.x; in[4*i+1] = vv.y; in[4*i+2] = vv.z; in[4*i+3] = vv.w;
        }
        const float4* ap = (const float4*)(g_A + node * H);
        #pragma unroll
        for (int i = 0; i < 8; i++) {
            float4 vv = ap[i];
            in[16+4*i] = vv.x; in[17+4*i] = vv.y; in[18+4*i] = vv.z; in[19+4*i] = vv.w;
        }
        float h[32];
        #pragma unroll
        for (int j = 0; j < 32; j++) {
            float acc = sbu1[j];
            #pragma unroll
            for (int k = 0; k < 48; k += 4) {
                float4 w = *(const float4*)&sWu1t[j * 48 + k];
                acc += in[k]*w.x + in[k+1]*w.y + in[k+2]*w.z + in[k+3]*w.w;
            }
            h[j] = lrelu(acc);
        }
        float o[16];
        #pragma unroll
        for (int j = 0; j < 16; j++) {
            float acc = sbu2[j];
            #pragma unroll
            for (int k = 0; k < 32; k += 4) {
                float4 w = *(const float4*)&sWu2t[j * 32 + k];
                acc += h[k]*w.x + h[k+1]*w.y + h[k+2]*w.z + h[k+3]*w.w;
            }
            o[j] = lrelu(acc);
            smX[t * 17 + j] = o[j];
        }
        if (layer < 2) {
            float h2[32];
            #pragma unroll
            for (int j = 0; j < 32; j++) {
                float acc = sb1[j];
                #pragma unroll
                for (int k = 0; k < 16; k += 4) {
                    float4 w = *(const float4*)&sW1t[j * 16 + k];
                    acc += o[k]*w.x + o[k+1]*w.y + o[k+2]*w.z + o[k+3]*w.w;
                }
                h2[j] = lrelu(acc);
            }
            #pragma unroll
            for (int j = 0; j < 32; j++) {
                float acc = sb2[j];
                #pragma unroll
                for (int k = 0; k < 32; k += 4) {
                    float4 w = *(const float4*)&sW2t[j * 32 + k];
                    acc += h2[k]*w.x + h2[k+1]*w.y + h2[k+2]*w.z + h2[k+3]*w.w;
                }
                smM[t * 33 + j] = lrelu(acc);
            }
        }
    }
    __syncthreads();
    int nvalid = min(128, NTOT - base);
    for (int i = t; i < nvalid * D; i += 128) {
        int n = i >> 4, j = i & 15;
        g_x[base * D + i] = smX[n * 17 + j];
    }
    if (layer < 2) {
        for (int i = t; i < nvalid * H; i += 128) {
            int n = i >> 5, j = i & 31;
            g_M[base * H + i] = smM[n * 33 + j];
        }
    }
}

// ---------------- final: bfm = tanh(x_s @ Wo + bo), column sum-of-squares -------
__global__ void __launch_bounds__(256) final_kernel(const float* __restrict__ Wo,
                                                    const float* __restrict__ bo)
{
    __shared__ __align__(16) float sWot[16 * 16];
    __shared__ float sbo[16];
    __shared__ float ssum[16];

    int t = threadIdx.x;
    if (t < 256) { int k = t >> 4, j = t & 15; sWot[j * 16 + k] = Wo[t]; }
    if (t < 16) { sbo[t] = bo[t]; ssum[t] = 0.f; }
    __syncthreads();

    float sq[16];
    #pragma unroll
    for (int j = 0; j < 16; j++) sq[j] = 0.f;

    int gtid = blockIdx.x * blockDim.x + t;
    int n = gridDim.x * blockDim.x;
    for (int node = gtid; node < N_S; node += n) {
        float x[16];
        #pragma unroll
        for (int i = 0; i < 4; i++) {
            float4 v = ((const float4*)(g_x + node * D))[i];
            x[4*i] = v.x; x[4*i+1] = v.y; x[4*i+2] = v.z; x[4*i+3] = v.w;
        }
        float y[16];
        #pragma unroll
        for (int j = 0; j < 16; j++) {
            float acc = sbo[j];
            #pragma unroll
            for (int k = 0; k < 16; k += 4) {
                float4 w = *(const float4*)&sWot[j * 16 + k];
                acc += x[k]*w.x + x[k+1]*w.y + x[k+2]*w.z + x[k+3]*w.w;
            }
            y[j] = tanhf(acc);
            sq[j] += y[j] * y[j];
        }
        float4* op = (float4*)(g_bfm + node * D);
        #pragma unroll
        for (int i = 0; i < 4; i++)
            op[i] = make_float4(y[4*i], y[4*i+1], y[4*i+2], y[4*i+3]);
    }

    #pragma unroll
    for (int o = 16; o > 0; o >>= 1) {
        #pragma unroll
        for (int j = 0; j < 16; j++)
            sq[j] += __shfl_xor_sync(0xffffffffu, sq[j], o);
    }
    if ((t & 31) == 0) {
        #pragma unroll
        for (int j = 0; j < 16; j++) atomicAdd(&ssum[j], sq[j]);
    }
    __syncthreads();
    if (t < 16) atomicAdd(&g_ss[t], ssum[t]);
}

__global__ void scale_kernel()
{
    int tid = threadIdx.x;   // 16 threads
    int c = tid & 7;
    float nrm = sqrtf(g_ss[c] + g_ss[c + 8]);
    g_scale[tid] = (nrm > 1.0f) ? (1.0f / nrm) : 1.0f;
}

__global__ void out_kernel(float* __restrict__ out)
{
    int gtid = blockIdx.x * blockDim.x + threadIdx.x;
    int n = gridDim.x * blockDim.x;
    const int Q = (N_S * D) / 4;
    const float4* bfm4 = (const float4*)g_bfm;
    const float4* sc4 = (const float4*)g_scale;
    float4* out4 = (float4*)out;
    for (int i = gtid; i < Q; i += n) {
        float4 s = sc4[i & 3];
        float4 b = bfm4[i];
        b.x *= s.x; b.y *= s.y; b.z *= s.z; b.w *= s.w;
        out4[i] = b;
    }
}

// ---------------- launch --------------------------------------------------------
extern "C" void kernel_launch(void* const* d_in, const int* in_sizes, int n_in,
                              void* d_out, int out_size)
{
    const float* xs  = (const float*)d_in[0];
    const float* xi  = (const float*)d_in[1];
    const int* ei_si = (const int*)d_in[2];
    const int* ei_is = (const int*)d_in[3];
    const float* Wm1 = (const float*)d_in[4];
    const float* bm1 = (const float*)d_in[5];
    const float* Wm2 = (const float*)d_in[6];
    const float* bm2 = (const float*)d_in[7];
    const float* Wu1 = (const float*)d_in[8];
    const float* bu1 = (const float*)d_in[9];
    const float* Wu2 = (const float*)d_in[10];
    const float* bu2 = (const float*)d_in[11];
    const float* Wo  = (const float*)d_in[12];
    const float* bo  = (const float*)d_in[13];

    // CSR build (amortized over 3 layers, 2 relations)
    zero_kernel<<<256, 256>>>();
    hist_kernel<<<1184, 256>>>(ei_si, ei_is);
    scan1_kernel<<<NCHUNK, CHUNK>>>();
    scan2_kernel<<<1, 256>>>();
    scan3_kernel<<<NCHUNK, CHUNK>>>();
    fill_kernel<<<1184, 256>>>(ei_si, ei_is);

    msg0_kernel<<<(NTOT + 255) / 256, 256>>>(xs, xi, Wm1, bm1, Wm2, bm2);

    for (int l = 0; l < 3; l++) {
        gather_kernel<<<1184, 256>>>();
        upd_kernel<<<(NTOT + 127) / 128, 128>>>(xs, xi, Wu1, bu1, Wu2, bu2,
                                                Wm1, bm1, Wm2, bm2, l);
    }

    final_kernel<<<391, 256>>>(Wo, bo);
    scale_kernel<<<1, 16>>>();
    out_kernel<<<256, 256>>>((float*)d_out);
}